// round 15
// baseline (speedup 1.0000x reference)
#include <cuda_runtime.h>
#include <math.h>
#include <stdint.h>

#define O_   16
#define C_   64
#define NN   576
#define LL   1024
#define B_   8
#define CH   64
#define NCH  9
#define EPSN 1e-4f
#define XP   516       // float pitch per o row in X buffer (64*8 + 4 pad)

// Persistent scratch (no cudaMalloc). g_A rewritten bit-identically each
// launch; stale flags on graph replay are benign (idempotent writes).
__device__ float g_A[O_ * 81];
__device__ int   g_Aflag[O_];

// ---- smem float offsets ---------------------------------------------------
#define X_OFF  0        // [2][16*XP] = 16512 (builder scratch pre-loop; stats post)
#define US_OFF 16512    // [2][2048]  y2-part staged, combined in place
#define NB_OFF 20608    // [2][2048]
#define Z0_OFF 24704
#define S2_OFF 24736
#define SM_FLOATS 24768 // 99072 B

// ---------------------------------------------------------------------------
#define FMA2(acc_, x_, u_) \
    asm("fma.rn.f32x2 %0, %1, %2, %0;" : "+l"(acc_) : "l"(x_), "l"(u_))

__device__ __forceinline__ unsigned long long pk2(float a, float b) {
    unsigned long long r;
    asm("mov.b64 %0, {%1, %2};"
        : "=l"(r) : "r"(__float_as_uint(a)), "r"(__float_as_uint(b)));
    return r;
}
__device__ __forceinline__ void cp16(unsigned dst, const void* src) {
    asm volatile("cp.async.cg.shared.global [%0], [%1], 16;" :: "r"(dst), "l"(src));
}
__device__ __forceinline__ void cp4z(unsigned dst, const void* src, int pred) {
    asm volatile("cp.async.ca.shared.global [%0], [%1], 4, %2;"
                 :: "r"(dst), "l"(src), "r"(pred ? 4 : 0));
}
#define CP_COMMIT() asm volatile("cp.async.commit_group;")
#define CP_WAIT0()  asm volatile("cp.async.wait_group 0;")

// ---------------------------------------------------------------------------
// Blocks 0..15: fp32 symmetric-scaled inverse covariance for channel o.
// EXACT R13 table-based builder (known 127-reg configuration).
// Scratch S = X region (buf0, 8256 floats; needs ~5740). Runs pre-loop.
// ---------------------------------------------------------------------------
__device__ void build_A_block(const float* __restrict__ wgt, float* S, int o, int t) {
    float* sXp   = S;           // 576*9 = 5184
    float* parts = S + 5184;    // 243
    float* Cf    = S + 5440;    // 81
    float* Cm    = S + 5536;    // 171
    float* Dv    = S + 5712;    // 9
    float* fv    = S + 5728;    // 9

    for (int n = t; n < NN; n += 256) {
        float w1 = wgt[(o * NN + n) * 2 + 0];
        float w2 = wgt[(o * NN + n) * 2 + 1];
        float* d = sXp + n * 9;
        d[0] = 1.0f;
        d[1] = w1;        d[2] = w2;
        d[3] = w1 * w1;   d[4] = w2 * w2;
        d[5] = d[3] * w1; d[6] = d[4] * w2;
        d[7] = d[3] * d[3]; d[8] = d[4] * d[4];
    }
    __syncthreads();

    if (t < 243) {
        int pair = t / 3, sl = t - pair * 3;
        int p = pair / 9, q = pair - (pair / 9) * 9;
        float a0 = 0, a1 = 0, a2 = 0, a3 = 0;
        int n0 = sl * 192;
        for (int n = n0; n < n0 + 192; n += 4) {
            a0 += sXp[n * 9 + p]       * sXp[n * 9 + q];
            a1 += sXp[(n + 1) * 9 + p] * sXp[(n + 1) * 9 + q];
            a2 += sXp[(n + 2) * 9 + p] * sXp[(n + 2) * 9 + q];
            a3 += sXp[(n + 3) * 9 + p] * sXp[(n + 3) * 9 + q];
        }
        parts[t] = (a0 + a1) + (a2 + a3);
    }
    __syncthreads();
    if (t < 81) Cf[t] = parts[t * 3] + parts[t * 3 + 1] + parts[t * 3 + 2];
    __syncthreads();
    if (t < 9) Dv[t] = rsqrtf(Cf[t * 9 + t]);
    __syncthreads();
    if (t < 81) {
        int p = t / 9, q = t - 9 * (t / 9);
        Cm[p * 19 + q]     = Cf[t] * Dv[p] * Dv[q];
        Cm[p * 19 + 9 + q] = (p == q) ? 1.0f : 0.0f;
    }
    __syncthreads();

    for (int k = 0; k < 9; k++) {
        if (t < 9) fv[t] = Cm[t * 19 + k];
        __syncthreads();
        if (t < 19) Cm[k * 19 + t] *= (1.0f / fv[k]);
        __syncthreads();
        if (t < 171) {
            int ii = t / 19, jj = t - 19 * (t / 19);
            if (ii != k) Cm[ii * 19 + jj] -= fv[ii] * Cm[k * 19 + jj];
        }
        __syncthreads();
    }
    if (t < 81) {
        int p = t / 9, q = t - 9 * (t / 9);
        g_A[o * 81 + t] = Dv[p] * Cm[p * 19 + 9 + q] * Dv[q];
        __threadfence();
    }
    __syncthreads();
    if (t == 0) *((volatile int*)&g_Aflag[o]) = 1;
    __syncthreads();
}

// ---------------------------------------------------------------------------
// Stage chunk cc (mod-2): y2 zfill -> us, noise -> nb. Self-ownership:
// thread t stages exactly floats 4t..4t+3 (+1024) that it combines.
// ---------------------------------------------------------------------------
__device__ __forceinline__ void stage_chunk(
    int cc, int t, int i,
    unsigned us_b, unsigned nb_b,
    const float* __restrict__ y2b,
    const char*  __restrict__ nzb)
{
    int bi = cc & 1;
    #pragma unroll
    for (int g2 = 0; g2 < 2; g2++) {
        int gran = t + g2 * 256;
        int nl = gran >> 3;
        cp16(nb_b + bi * 8192 + gran * 16,
             nzb + ((size_t)(cc * CH + nl)) * (LL * 4) + (gran & 7) * 16);
    }
    #pragma unroll
    for (int q = 0; q < 8; q++) {
        int k = 4 * t + (q & 3) + (q >> 2) * 1024;
        int n  = cc * CH + (k >> 5);
        int j  = k & 31;
        int ch = n / 9;
        int kk = n - ch * 9;
        int ki = kk / 3, kj = kk - ki * 3;
        int rr = i + ki - 1;
        int cl = j + kj - 1;
        int ok = ((unsigned)rr < 32u) & ((unsigned)cl < 32u);
        const float* srcp = ok ? (y2b + (ch * 32 + rr) * 32 + cl) : y2b;
        cp4z(us_b + bi * 8192 + k * 4, srcp, ok);
    }
}

// ---------------------------------------------------------------------------
// Fused kernel. Block = (b, image row i). 256 threads:
// h = t>>7 (n-half), r = t&127, o = r>>3, g = r&7, j0 = 4g.
// Per chunk: wait0 -> combine(in-place us) -> prep X powers -> stage(c+1)
//           -> commit -> SYNC -> compute -> SYNC   (R8 two-barrier, mod-2)
// Compute: 16 FMA2 + 4 pk2 + 3 LDS.128 per nl (powers precomputed in X).
// ---------------------------------------------------------------------------
__global__ void __launch_bounds__(256, 2) srn_main(
    const float* __restrict__ y2,
    const float* __restrict__ wgt,
    const float* __restrict__ noise,
    float* __restrict__ out)
{
    extern __shared__ float sm[];
    float* Xs  = sm;                 // 2 x 16*XP
    float* us  = sm + US_OFF;        // 2 x 2048
    float* nb  = sm + NB_OFF;        // 2 x 2048
    float* z0s = sm + Z0_OFF;
    float* s2s = sm + S2_OFF;

    unsigned sbase = (unsigned)__cvta_generic_to_shared(sm);
    const unsigned us_b = sbase + US_OFF * 4;
    const unsigned nb_b = sbase + NB_OFF * 4;

    int b = blockIdx.x >> 5;
    int i = blockIdx.x & 31;
    int t = threadIdx.x;
    int h = t >> 7;
    int r = t & 127;
    int o = r >> 3;
    int g = r & 7;
    int j0 = g * 4;

    unsigned long long acc[16];
    #pragma unroll
    for (int k = 0; k < 16; k++) acc[k] = 0ULL;
    float sa1[4] = {0, 0, 0, 0};
    float sa2[4] = {0, 0, 0, 0};

    const float* y2b = y2 + b * (C_ * 32 * 32);
    const char*  nzb = (const char*)(noise + (size_t)b * (NN * LL) + (size_t)i * 32);

    stage_chunk(0, t, i, us_b, nb_b, y2b, nzb);
    CP_COMMIT();

    // blocks 0..15: build the 9x9 inverse covariance (scratch: X buf0)
    if (blockIdx.x < O_)
        build_A_block(wgt, Xs, blockIdx.x, t);

    for (int c = 0; c < NCH; c++) {
        int bi = c & 1;
        CP_WAIT0();                 // stage(c) landed (self-visible)

        // ---- combine own staged floats in place: u = y2part + eps*noise ----
        #pragma unroll
        for (int hf = 0; hf < 2; hf++) {
            int kb = bi * 2048 + 4 * t + hf * 1024;
            float4 yv = *(const float4*)(us + kb);
            float4 nv = *(const float4*)(nb + kb);
            float v0 = fmaf(EPSN, nv.x, yv.x);
            float v1 = fmaf(EPSN, nv.y, yv.y);
            float v2 = fmaf(EPSN, nv.z, yv.z);
            float v3 = fmaf(EPSN, nv.w, yv.w);
            sa1[0] += v0; sa2[0] += v0 * v0;
            sa1[1] += v1; sa2[1] += v1 * v1;
            sa1[2] += v2; sa2[2] += v2 * v2;
            sa1[3] += v3; sa2[3] += v3 * v3;
            *(float4*)(us + kb) = make_float4(v0, v1, v2, v3);
        }

        // ---- prep X powers for this chunk: thread -> o2 = t>>4, 4 nl ----
        {
            int o2  = t >> 4;
            int nl0 = (t & 15) * 4;
            const float2* wg = (const float2*)wgt + (size_t)(o2 * NN + c * CH + nl0);
            float* xd = Xs + bi * (O_ * XP) + o2 * XP + nl0 * 8;
            #pragma unroll
            for (int e = 0; e < 4; e++) {
                float2 wv2 = __ldg(wg + e);
                float a1 = wv2.x, a2 = wv2.y;
                float b1 = a1 * a1, b2 = a2 * a2;
                float c1 = b1 * a1, c2 = b2 * a2;
                float d1 = b1 * b1, d2 = b2 * b2;
                *(float4*)(xd + e * 8)     = make_float4(a1, a2, b1, b2);
                *(float4*)(xd + e * 8 + 4) = make_float4(c1, c2, d1, d2);
            }
        }

        if (c + 1 < NCH)
            stage_chunk(c + 1, t, i, us_b, nb_b, y2b, nzb);
        CP_COMMIT();
        __syncthreads();            // us[bi] + X[bi] visible to all

        // ---- compute over this thread's n-half (32 n) ----
        const float* up = us + bi * 2048 + h * 1024;
        const float* xp = Xs + bi * (O_ * XP) + o * XP + h * 32 * 8;
        #pragma unroll 4
        for (int nl = 0; nl < 32; nl++) {
            float4 uu = *(const float4*)(up + nl * 32 + j0);
            ulonglong2 xA = *(const ulonglong2*)(xp + nl * 8);      // (m1, m2)
            ulonglong2 xB = *(const ulonglong2*)(xp + nl * 8 + 4);  // (m3, m4)
            unsigned long long ua = pk2(uu.x, uu.x);
            unsigned long long ub = pk2(uu.y, uu.y);
            unsigned long long uc = pk2(uu.z, uu.z);
            unsigned long long ud = pk2(uu.w, uu.w);
            FMA2(acc[0],  xA.x, ua); FMA2(acc[1],  xA.y, ua);
            FMA2(acc[2],  xB.x, ua); FMA2(acc[3],  xB.y, ua);
            FMA2(acc[4],  xA.x, ub); FMA2(acc[5],  xA.y, ub);
            FMA2(acc[6],  xB.x, ub); FMA2(acc[7],  xB.y, ub);
            FMA2(acc[8],  xA.x, uc); FMA2(acc[9],  xA.y, uc);
            FMA2(acc[10], xB.x, uc); FMA2(acc[11], xB.y, uc);
            FMA2(acc[12], xA.x, ud); FMA2(acc[13], xA.y, ud);
            FMA2(acc[14], xB.x, ud); FMA2(acc[15], xB.y, ud);
        }
        __syncthreads();            // compute done before buffer reuse
    }

    // ---- stats partials + acc partials (overlay X buf0) ----
    // P1 = sm[0..1055], P2 = sm[1088..2143], accred = sm[2176..6399]
    {
        int slot = t >> 3;
        #pragma unroll
        for (int q = 0; q < 4; q++) {
            int jq = 4 * (t & 7) + q;
            sm[jq * 33 + slot]        = sa1[q];
            sm[1088 + jq * 33 + slot] = sa2[q];
        }
    }
    if (h == 1) {
        float* base = sm + 2176 + r * 33;
        #pragma unroll
        for (int k = 0; k < 16; k++) {
            base[2 * k]     = __uint_as_float((unsigned)acc[k]);
            base[2 * k + 1] = __uint_as_float((unsigned)(acc[k] >> 32));
        }
    }
    __syncthreads();

    if (t < 32) {
        float a = 0.0f, bb = 0.0f;
        #pragma unroll
        for (int s = 0; s < 32; s++) {
            a  += sm[t * 33 + s];
            bb += sm[1088 + t * 33 + s];
        }
        z0s[t] = a;
        s2s[t] = bb;
    }
    __syncthreads();

    if (h == 0) {
        const float* base = sm + 2176 + r * 33;
        float wv[4][8];
        #pragma unroll
        for (int loc = 0; loc < 4; loc++)
            #pragma unroll
            for (int pp = 0; pp < 4; pp++) {
                unsigned long long a = acc[loc * 4 + pp];
                int k = loc * 4 + pp;
                wv[loc][2 * pp]     = __uint_as_float((unsigned)a)         + base[2 * k];
                wv[loc][2 * pp + 1] = __uint_as_float((unsigned)(a >> 32)) + base[2 * k + 1];
            }

        // wait for this o's inverse covariance (normally long done)
        {
            volatile int* fl = g_Aflag + o;
            while (*fl == 0) {}
        }
        __threadfence();

        float w0v[4], wAw[4];
        #pragma unroll
        for (int loc = 0; loc < 4; loc++) {
            w0v[loc] = z0s[j0 + loc];
            wAw[loc] = 0.0f;
        }
        const float* A = g_A + o * 81;
        #pragma unroll
        for (int p = 0; p < 9; p++) {
            float tp[4] = {0.0f, 0.0f, 0.0f, 0.0f};
            #pragma unroll
            for (int q = 0; q < 9; q++) {
                float a = A[p * 9 + q];
                #pragma unroll
                for (int loc = 0; loc < 4; loc++) {
                    float v = (q == 0) ? w0v[loc] : wv[loc][q - 1];
                    tp[loc] = fmaf(a, v, tp[loc]);
                }
            }
            #pragma unroll
            for (int loc = 0; loc < 4; loc++) {
                float v = (p == 0) ? w0v[loc] : wv[loc][p - 1];
                wAw[loc] = fmaf(tp[loc], v, wAw[loc]);
            }
        }

        float4 res;
        #pragma unroll
        for (int loc = 0; loc < 4; loc++) {
            float S2 = s2s[j0 + loc];
            float z0 = w0v[loc];
            float denom = S2 - z0 * z0 * (1.0f / 576.0f);
            float err = (S2 - wAw[loc]) * (575.0f / 576.0f) / denom;
            ((float*)&res)[loc] = expf(-err);
        }
        *(float4*)(out + ((size_t)(b * 16 + o)) * 1024 + i * 32 + j0) = res;
    }
}

// ---------------------------------------------------------------------------
extern "C" void kernel_launch(void* const* d_in, const int* in_sizes, int n_in,
                              void* d_out, int out_size) {
    const float* y2 = nullptr;
    const float* w  = nullptr;
    const float* nz = nullptr;
    for (int k = 0; k < n_in; k++) {
        if      (in_sizes[k] == 524288)  y2 = (const float*)d_in[k];
        else if (in_sizes[k] == 18432)   w  = (const float*)d_in[k];
        else if (in_sizes[k] == 4718592) nz = (const float*)d_in[k];
    }
    if (!y2 || !w || !nz) {
        y2 = (const float*)d_in[0];
        w  = (const float*)d_in[1];
        nz = (const float*)d_in[2];
    }

    const int smem_bytes = SM_FLOATS * 4;   // 99072 B
    cudaFuncSetAttribute(srn_main, cudaFuncAttributeMaxDynamicSharedMemorySize, smem_bytes);
    srn_main<<<B_ * 32, 256, smem_bytes>>>(y2, w, nz, (float*)d_out);
}